// round 12
// baseline (speedup 1.0000x reference)
#include <cuda_runtime.h>

#define Nn   1024
#define Cc   64
#define HID  128
#define TS   16                         // output sub-tile edge
#define NTS  (Nn / TS)                  // 64
#define NUNITS (NTS * (NTS + 1) / 2)    // 2080
#define PNCH 32                         // n-cols per prep block

// interleaved: g_E[h*Nn + n] = (exp(2*pi[h,n]), exp(2*pj[h,n]))
__device__ float2 g_E[HID * Nn];
__device__ float  g_sw2;                // sum of W2

// reciprocal on the MUFU pipe
__device__ __forceinline__ float rcp_mufu(float d) {
    float r;
    asm("rcp.approx.f32 %0, %1;" : "=f"(r) : "f"(d));
    return r;
}
// reciprocal on the FMA pipe: bit-hack seed + 2 Newton (rel err ~1e-6)
__device__ __forceinline__ float rcp_nr(float d) {
    float r = __uint_as_float(0x7EF311C7u - __float_as_uint(d));
    r = r * (2.0f - d * r);
    r = r * (2.0f - d * r);
    return r;
}

// ---------------------------------------------------------------------------
// prep: pi[h,n] = sum_c W1[h,Cc+c]*tanh(x[c,n]) + b1[h]; pj likewise.
// Emits (exp(2*pi), exp(2*pj)). Warp-uniform h, lane = n (coalesced).
// Block (0,0) also reduces sum(W2) -> g_sw2.
// ---------------------------------------------------------------------------
__global__ __launch_bounds__(256) void prep_kernel(const float* __restrict__ x,
                                                   const float* __restrict__ W1,
                                                   const float* __restrict__ b1,
                                                   const float* __restrict__ W2) {
    __shared__ float t_s[Cc][PNCH];
    const int n0   = blockIdx.x * PNCH;
    const int tid  = threadIdx.x;
    const int lane = tid & 31;
    const int w    = tid >> 5;

    for (int k = tid; k < Cc * PNCH; k += 256) {
        int c = k >> 5, n = k & 31;
        t_s[c][n] = tanhf(x[c * Nn + n0 + n]);
    }
    __syncthreads();

#pragma unroll
    for (int g = 0; g < 4; g++) {
        const int h = blockIdx.y * 32 + w * 4 + g;
        const float bb = b1[h];
        float acci = bb, accj = 0.0f;
#pragma unroll
        for (int c = 0; c < Cc; c++) {
            float wj = W1[h * (2 * Cc) + c];        // warp-uniform broadcast
            float wi = W1[h * (2 * Cc) + Cc + c];
            float t  = t_s[c][lane];
            accj = fmaf(wj, t, accj);
            acci = fmaf(wi, t, acci);
        }
        float Ei = fminf(expf(2.0f * acci), 1e15f);
        float Ej = fminf(expf(2.0f * accj), 1e15f);
        g_E[h * Nn + n0 + lane] = make_float2(Ei, Ej);
    }

    // block (0,0): reduce sum(W2)
    if (blockIdx.x == 0 && blockIdx.y == 0 && tid < 32) {
        float s = 0.0f;
        for (int k = lane; k < HID; k += 32) s += W2[k];
#pragma unroll
        for (int o = 16; o; o >>= 1) s += __shfl_xor_sync(0xffffffffu, s, o);
        if (lane == 0) g_sw2 = s;
    }

    __threadfence();
    __syncthreads();
    asm volatile("griddepcontrol.launch_dependents;" ::: "memory");
}

// ---------------------------------------------------------------------------
// pair: 16x16 triangular unit, 256 threads = 2 h-groups x 128.
// Thread (g, ii, jj2): 1 i x 2 j over 64 h. Per h, 4 terms:
//   tanh(pi_a+pj_b) = 1 - 2/(Ei_a*Ej_b + 1)
// acc = sum w2 * r ; out = 2*(sum(W2) + b2 - acc_total).
// rcp: 1 of 4 on FMA pipe (Newton), 3 of 4 on MUFU — pipe-balanced.
// ---------------------------------------------------------------------------
__global__ __launch_bounds__(256) void pair_kernel(const float* __restrict__ W2,
                                                   const float* __restrict__ b2,
                                                   float* __restrict__ out) {
    __shared__ __align__(16) float2 pS[HID][2 * TS];   // [h][0..15]=i, [16..31]=j
    __shared__ float w2s[HID];
    __shared__ float red[TS * TS];

    // triangular decode
    int rem = blockIdx.x, a = 0, len = NTS;
    while (rem >= len) { rem -= len; a++; len--; }
    const int b  = a + rem;
    const int i0 = a * TS, j0 = b * TS;

    const int tid = threadIdx.x;
    if (tid < HID) w2s[tid] = W2[tid];
    const float b2v = b2[0];

    asm volatile("griddepcontrol.wait;" ::: "memory");
    const float sw2 = g_sw2;

    // stage: 128 h x (16 i + 16 j) float2, as float4
    for (int t = tid; t < HID * 16; t += 256) {
        int h    = t >> 4;
        int q    = t & 15;
        int side = q >> 3;
        int c    = (q & 7) * 2;
        int src  = side ? j0 : i0;
        float4 v = *(const float4*)&g_E[h * Nn + src + c];
        *(float4*)&pS[h][side * TS + c] = v;
    }
    __syncthreads();

    const int g   = tid >> 7;        // h-group 0/1
    const int t2  = tid & 127;
    const int ii  = t2 >> 3;         // 0..15
    const int jj2 = t2 & 7;          // 0..7 -> j = 2*jj2, 2*jj2+1
    const int h0  = g * 64;

    float acc0 = 0.0f, acc1 = 0.0f;
#pragma unroll 8
    for (int hl = 0; hl < 64; hl++) {
        const int H = h0 + hl;
        float2 ai = pS[H][ii];                             // (Ei_i, Ej_i)
        float4 aj = *(const float4*)&pS[H][TS + 2 * jj2];  // (Ei_j0,Ej_j0,Ei_j1,Ej_j1)
        float  w  = w2s[H];

        float d1 = fmaf(ai.x, aj.y, 1.0f);   // dir1, j0
        float d2 = fmaf(aj.x, ai.y, 1.0f);   // dir2, j0
        float d3 = fmaf(ai.x, aj.w, 1.0f);   // dir1, j1
        float d4 = fmaf(aj.z, ai.y, 1.0f);   // dir2, j1

        float r1 = rcp_nr(d1);               // FMA-pipe path (1 of 4)
        float r2 = rcp_mufu(d2);
        float r3 = rcp_mufu(d3);
        float r4 = rcp_mufu(d4);

        acc0 = fmaf(w, r1, acc0);
        acc0 = fmaf(w, r2, acc0);
        acc1 = fmaf(w, r3, acc1);
        acc1 = fmaf(w, r4, acc1);
    }

    // combine h-groups
    if (g == 0) {
        red[ii * TS + jj2 * 2 + 0] = acc0;
        red[ii * TS + jj2 * 2 + 1] = acc1;
    }
    __syncthreads();
    if (g == 1) {
        const float t0 = red[ii * TS + jj2 * 2 + 0] + acc0;
        const float t1 = red[ii * TS + jj2 * 2 + 1] + acc1;
        const float v0 = 2.0f * (sw2 + b2v - t0);
        const float v1 = 2.0f * (sw2 + b2v - t1);
        const int gi = i0 + ii;
        const int gj = j0 + jj2 * 2;
        *(float2*)&out[gi * Nn + gj] = make_float2(v0, v1);  // upper, coalesced
        out[(gj + 0) * Nn + gi] = v0;                        // mirror
        out[(gj + 1) * Nn + gi] = v1;
    }
}

extern "C" void kernel_launch(void* const* d_in, const int* in_sizes, int n_in,
                              void* d_out, int out_size) {
    const float* x  = (const float*)d_in[0];
    const float* W1 = (const float*)d_in[1];
    const float* b1 = (const float*)d_in[2];
    const float* W2 = (const float*)d_in[3];
    const float* b2 = (const float*)d_in[4];
    float* out = (float*)d_out;

    prep_kernel<<<dim3(32, 4), 256>>>(x, W1, b1, W2);

    cudaLaunchConfig_t cfg = {};
    cfg.gridDim  = dim3(NUNITS);
    cfg.blockDim = dim3(256);
    cfg.dynamicSmemBytes = 0;
    cfg.stream = 0;
    cudaLaunchAttribute attr[1];
    attr[0].id = cudaLaunchAttributeProgrammaticStreamSerialization;
    attr[0].val.programmaticStreamSerializationAllowed = 1;
    cfg.attrs = attr;
    cfg.numAttrs = 1;
    cudaLaunchKernelEx(&cfg, pair_kernel, W2, b2, (float*)out);
}

// round 13
// speedup vs baseline: 1.1216x; 1.1216x over previous
#include <cuda_runtime.h>

#define Nn   1024
#define Cc   64
#define HID  128
#define TS   16                         // output sub-tile edge
#define NTS  (Nn / TS)                  // 64
#define NUNITS (NTS * (NTS + 1) / 2)    // 2080
#define PNCH 32                         // n-cols per prep block

// interleaved: g_E[h*Nn + n] = (exp(2*pi[h,n]), exp(2*pj[h,n]))
__device__ float2 g_E[HID * Nn];

__device__ __forceinline__ float rcp_mufu(float d) {
    float r;
    asm("rcp.approx.f32 %0, %1;" : "=f"(r) : "f"(d));
    return r;
}

// ---------------------------------------------------------------------------
// prep: pi[h,n] = sum_c W1[h,Cc+c]*tanh(x[c,n]) + b1[h]; pj likewise.
// Emits (exp(2*pi), exp(2*pj)), clamped. Warp-uniform h, lane = n.
// ---------------------------------------------------------------------------
__global__ __launch_bounds__(256) void prep_kernel(const float* __restrict__ x,
                                                   const float* __restrict__ W1,
                                                   const float* __restrict__ b1) {
    __shared__ float t_s[Cc][PNCH];
    const int n0   = blockIdx.x * PNCH;
    const int tid  = threadIdx.x;
    const int lane = tid & 31;
    const int w    = tid >> 5;

    for (int k = tid; k < Cc * PNCH; k += 256) {
        int c = k >> 5, n = k & 31;
        t_s[c][n] = tanhf(x[c * Nn + n0 + n]);
    }
    __syncthreads();

#pragma unroll
    for (int g = 0; g < 4; g++) {
        const int h = blockIdx.y * 32 + w * 4 + g;
        const float bb = b1[h];
        float acci = bb, accj = 0.0f;
#pragma unroll
        for (int c = 0; c < Cc; c++) {
            float wj = W1[h * (2 * Cc) + c];        // warp-uniform broadcast
            float wi = W1[h * (2 * Cc) + Cc + c];
            float t  = t_s[c][lane];
            accj = fmaf(wj, t, accj);
            acci = fmaf(wi, t, acci);
        }
        float Ei = fminf(expf(2.0f * acci), 1e8f);
        float Ej = fminf(expf(2.0f * accj), 1e8f);
        g_E[h * Nn + n0 + lane] = make_float2(Ei, Ej);
    }

    __threadfence();
    __syncthreads();
    asm volatile("griddepcontrol.launch_dependents;" ::: "memory");
}

// ---------------------------------------------------------------------------
// pair: 16x16 triangular unit, 256 threads = 2 h-groups x 128.
// Thread (g, ii, jj2): 1 i x 2 j over 64 h. Per (h,j) ONE combined term:
//   A1 = Ei_i*Ej_j + 1 ; B1 = Ei_j*Ej_i + 1 ; D = A1*B1
//   tanh(pi_i+pj_j) + tanh(pi_j+pj_i) = 2*(D - A1 - B1)/D
//   acc += w2[h] * (D - A1 - B1) / D      (one MUFU rcp per pair)
//   out[i,j] = out[j,i] = 2*(acc_total + b2)
// ---------------------------------------------------------------------------
__global__ __launch_bounds__(256) void pair_kernel(const float* __restrict__ W2,
                                                   const float* __restrict__ b2,
                                                   float* __restrict__ out) {
    __shared__ __align__(16) float2 pS[HID][2 * TS];   // [h][0..15]=i, [16..31]=j
    __shared__ float w2s[HID];
    __shared__ float red[TS * TS];

    // triangular decode
    int rem = blockIdx.x, a = 0, len = NTS;
    while (rem >= len) { rem -= len; a++; len--; }
    const int b  = a + rem;
    const int i0 = a * TS, j0 = b * TS;

    const int tid = threadIdx.x;
    if (tid < HID) w2s[tid] = W2[tid];
    const float b2v = b2[0];

    asm volatile("griddepcontrol.wait;" ::: "memory");

    // stage: 128 h x (16 i + 16 j) float2, as float4
    for (int t = tid; t < HID * 16; t += 256) {
        int h    = t >> 4;
        int q    = t & 15;
        int side = q >> 3;
        int c    = (q & 7) * 2;
        int src  = side ? j0 : i0;
        float4 v = *(const float4*)&g_E[h * Nn + src + c];
        *(float4*)&pS[h][side * TS + c] = v;
    }
    __syncthreads();

    const int g   = tid >> 7;        // h-group 0/1
    const int t2  = tid & 127;
    const int ii  = t2 >> 3;         // 0..15
    const int jj2 = t2 & 7;          // 0..7 -> j = 2*jj2, 2*jj2+1
    const int h0  = g * 64;

    float acc0 = 0.0f, acc1 = 0.0f;
#pragma unroll 8
    for (int hl = 0; hl < 64; hl++) {
        const int H = h0 + hl;
        float2 ai = pS[H][ii];                             // (Ei_i, Ej_i)
        float4 aj = *(const float4*)&pS[H][TS + 2 * jj2];  // (Ei_j0,Ej_j0,Ei_j1,Ej_j1)
        float  w  = w2s[H];

        // j0
        float A1 = fmaf(ai.x, aj.y, 1.0f);
        float B1 = fmaf(aj.x, ai.y, 1.0f);
        float D  = A1 * B1;
        float S  = A1 + B1;
        float nu = D - S;
        float rc = rcp_mufu(D);
        acc0 = fmaf(w * nu, rc, acc0);

        // j1
        float A1b = fmaf(ai.x, aj.w, 1.0f);
        float B1b = fmaf(aj.z, ai.y, 1.0f);
        float Db  = A1b * B1b;
        float Sb  = A1b + B1b;
        float nub = Db - Sb;
        float rcb = rcp_mufu(Db);
        acc1 = fmaf(w * nub, rcb, acc1);
    }

    // combine h-groups
    if (g == 0) {
        red[ii * TS + jj2 * 2 + 0] = acc0;
        red[ii * TS + jj2 * 2 + 1] = acc1;
    }
    __syncthreads();
    if (g == 1) {
        const float v0 = 2.0f * (red[ii * TS + jj2 * 2 + 0] + acc0 + b2v);
        const float v1 = 2.0f * (red[ii * TS + jj2 * 2 + 1] + acc1 + b2v);
        const int gi = i0 + ii;
        const int gj = j0 + jj2 * 2;
        *(float2*)&out[gi * Nn + gj] = make_float2(v0, v1);  // upper, coalesced
        out[(gj + 0) * Nn + gi] = v0;                        // mirror
        out[(gj + 1) * Nn + gi] = v1;
    }
}

extern "C" void kernel_launch(void* const* d_in, const int* in_sizes, int n_in,
                              void* d_out, int out_size) {
    const float* x  = (const float*)d_in[0];
    const float* W1 = (const float*)d_in[1];
    const float* b1 = (const float*)d_in[2];
    const float* W2 = (const float*)d_in[3];
    const float* b2 = (const float*)d_in[4];
    float* out = (float*)d_out;

    prep_kernel<<<dim3(32, 4), 256>>>(x, W1, b1);

    cudaLaunchConfig_t cfg = {};
    cfg.gridDim  = dim3(NUNITS);
    cfg.blockDim = dim3(256);
    cfg.dynamicSmemBytes = 0;
    cfg.stream = 0;
    cudaLaunchAttribute attr[1];
    attr[0].id = cudaLaunchAttributeProgrammaticStreamSerialization;
    attr[0].val.programmaticStreamSerializationAllowed = 1;
    cfg.attrs = attr;
    cfg.numAttrs = 1;
    cudaLaunchKernelEx(&cfg, pair_kernel, W2, b2, (float*)out);
}

// round 14
// speedup vs baseline: 1.1472x; 1.0228x over previous
#include <cuda_runtime.h>

#define Nn   1024
#define Cc   64
#define HID  128
#define TS   16
#define NTS  (Nn / TS)                  // 64
#define NUNITS (NTS * (NTS + 1) / 2)    // 2080
#define PNCH 32

typedef unsigned long long u64;

// i-side interleaved: g_p[h*Nn+n] = (Ei, Ej);  j-side pair arrays
__device__ float2 g_p  [HID * Nn];
__device__ float2 g_eip[HID * Nn / 2];   // (Ei_n, Ei_{n+1}), n even
__device__ float2 g_ejp[HID * Nn / 2];   // (Ej_n, Ej_{n+1}), n even

__device__ __forceinline__ float rcp_mufu(float d) {
    float r; asm("rcp.approx.f32 %0, %1;" : "=f"(r) : "f"(d)); return r;
}
__device__ __forceinline__ u64 pack2(float lo, float hi) {
    u64 r; asm("mov.b64 %0, {%1, %2};" : "=l"(r) : "f"(lo), "f"(hi)); return r;
}
__device__ __forceinline__ void unpack2(u64 v, float& lo, float& hi) {
    asm("mov.b64 {%0, %1}, %2;" : "=f"(lo), "=f"(hi) : "l"(v));
}
__device__ __forceinline__ u64 fma2(u64 a, u64 b, u64 c) {
    u64 d; asm("fma.rn.f32x2 %0, %1, %2, %3;" : "=l"(d) : "l"(a), "l"(b), "l"(c)); return d;
}
__device__ __forceinline__ u64 mul2(u64 a, u64 b) {
    u64 d; asm("mul.rn.f32x2 %0, %1, %2;" : "=l"(d) : "l"(a), "l"(b)); return d;
}
__device__ __forceinline__ u64 add2(u64 a, u64 b) {
    u64 d; asm("add.rn.f32x2 %0, %1, %2;" : "=l"(d) : "l"(a), "l"(b)); return d;
}

#define ONE2  0x3F8000003F800000ULL
#define NEG12 0xBF800000BF800000ULL

// ---------------------------------------------------------------------------
// prep: pi/pj GEMV (precise tanhf), emits E = exp(2*p) in interleaved +
// j-pair layouts. Warp-uniform h, lane = n.
// ---------------------------------------------------------------------------
__global__ __launch_bounds__(256) void prep_kernel(const float* __restrict__ x,
                                                   const float* __restrict__ W1,
                                                   const float* __restrict__ b1) {
    __shared__ float t_s[Cc][PNCH];
    const int n0   = blockIdx.x * PNCH;
    const int tid  = threadIdx.x;
    const int lane = tid & 31;
    const int w    = tid >> 5;

    for (int k = tid; k < Cc * PNCH; k += 256) {
        int c = k >> 5, n = k & 31;
        t_s[c][n] = tanhf(x[c * Nn + n0 + n]);
    }
    __syncthreads();

#pragma unroll
    for (int g = 0; g < 4; g++) {
        const int h = blockIdx.y * 32 + w * 4 + g;
        const float bb = b1[h];
        float acci = bb, accj = 0.0f;
#pragma unroll
        for (int c = 0; c < Cc; c++) {
            float wj = W1[h * (2 * Cc) + c];
            float wi = W1[h * (2 * Cc) + Cc + c];
            float t  = t_s[c][lane];
            accj = fmaf(wj, t, accj);
            acci = fmaf(wi, t, acci);
        }
        float Ei = fminf(expf(2.0f * acci), 1e8f);
        float Ej = fminf(expf(2.0f * accj), 1e8f);
        const int n = n0 + lane;
        g_p[h * Nn + n] = make_float2(Ei, Ej);
        float EiN = __shfl_down_sync(0xffffffffu, Ei, 1);
        float EjN = __shfl_down_sync(0xffffffffu, Ej, 1);
        if ((lane & 1) == 0) {
            g_eip[h * (Nn >> 1) + (n >> 1)] = make_float2(Ei, EiN);
            g_ejp[h * (Nn >> 1) + (n >> 1)] = make_float2(Ej, EjN);
        }
    }

    __threadfence();
    __syncthreads();
    asm volatile("griddepcontrol.launch_dependents;" ::: "memory");
}

// ---------------------------------------------------------------------------
// pair: 16x16 triangular unit, 256 threads = 2 h-groups x 128.
// Thread (g, ii, jj2): 1 i x packed-2 j over 64 h. Per h (f32x2 lanes = j0,j1):
//   A1 = Ei_i*Ej_j + 1 ; B1 = Ei_j*Ej_i + 1 ; D = A1*B1
//   acc += w2[h]*(D - A1 - B1)/D          [ = w2*(tanh+tanh)/2 ]
//   out = 2*(accTot + b2)
// ---------------------------------------------------------------------------
__global__ __launch_bounds__(256) void pair_kernel(const float* __restrict__ W2,
                                                   const float* __restrict__ b2,
                                                   float* __restrict__ out) {
    __shared__ __align__(16) float2 iS [HID][TS];       // (Ei_i, Ej_i)  16KB
    __shared__ __align__(16) float2 bjS[HID][TS / 2];   // Ej j-pairs     8KB
    __shared__ __align__(16) float2 biS[HID][TS / 2];   // Ei j-pairs     8KB
    __shared__ __align__(8)  float2 w2d[HID];           // dup(w2)        1KB
    __shared__ float red[TS * TS];

    int rem = blockIdx.x, a = 0, len = NTS;
    while (rem >= len) { rem -= len; a++; len--; }
    const int b  = a + rem;
    const int i0 = a * TS, j0 = b * TS;

    const int tid = threadIdx.x;
    if (tid < HID) { float w = W2[tid]; w2d[tid] = make_float2(w, w); }
    const float b2v = b2[0];

    asm volatile("griddepcontrol.wait;" ::: "memory");

    // stage: iS 1024 float4, bj/bi 512 float4 each
    for (int t = tid; t < 2048; t += 256) {
        if (t < 1024) {
            int h = t >> 3, c2 = (t & 7) * 2;
            *(float4*)&iS[h][c2] = *(const float4*)&g_p[h * Nn + i0 + c2];
        } else {
            int k   = t - 1024;
            int sel = k >> 9;                 // 0 = Ej pairs, 1 = Ei pairs
            int m   = k & 511;
            int h   = m >> 2, c2 = (m & 3) * 2;
            const float2* src = sel ? g_eip : g_ejp;
            float4 v = *(const float4*)&src[h * (Nn >> 1) + (j0 >> 1) + c2];
            if (sel) *(float4*)&biS[h][c2] = v;
            else     *(float4*)&bjS[h][c2] = v;
        }
    }
    __syncthreads();

    const int g   = tid >> 7;
    const int t2  = tid & 127;
    const int ii  = t2 >> 3;         // 0..15
    const int jj2 = t2 & 7;          // 0..7 -> j = 2*jj2, 2*jj2+1
    const int h0  = g * 64;

    u64 acc = 0;                      // packed (acc_j0, acc_j1)
#pragma unroll 8
    for (int hl = 0; hl < 64; hl++) {
        const int H = h0 + hl;
        float2 ai = iS[H][ii];
        u64 bj = *(const u64*)&bjS[H][jj2];
        u64 bi = *(const u64*)&biS[H][jj2];
        u64 wd = *(const u64*)&w2d[H];
        u64 eid = pack2(ai.x, ai.x);
        u64 ejd = pack2(ai.y, ai.y);

        u64 A1 = fma2(eid, bj, ONE2);
        u64 B1 = fma2(bi, ejd, ONE2);
        u64 D  = mul2(A1, B1);
        u64 S  = add2(A1, B1);
        u64 nu = fma2(S, NEG12, D);     // D - S

        float d0, d1; unpack2(D, d0, d1);
        u64 rc = pack2(rcp_mufu(d0), rcp_mufu(d1));
        u64 wn = mul2(nu, wd);
        acc = fma2(wn, rc, acc);
    }

    float acc0, acc1; unpack2(acc, acc0, acc1);

    if (g == 0) {
        red[ii * TS + jj2 * 2 + 0] = acc0;
        red[ii * TS + jj2 * 2 + 1] = acc1;
    }
    __syncthreads();
    if (g == 1) {
        const float v0 = 2.0f * (red[ii * TS + jj2 * 2 + 0] + acc0 + b2v);
        const float v1 = 2.0f * (red[ii * TS + jj2 * 2 + 1] + acc1 + b2v);
        const int gi = i0 + ii;
        const int gj = j0 + jj2 * 2;
        *(float2*)&out[gi * Nn + gj] = make_float2(v0, v1);
        out[(gj + 0) * Nn + gi] = v0;
        out[(gj + 1) * Nn + gi] = v1;
    }
}

extern "C" void kernel_launch(void* const* d_in, const int* in_sizes, int n_in,
                              void* d_out, int out_size) {
    const float* x  = (const float*)d_in[0];
    const float* W1 = (const float*)d_in[1];
    const float* b1 = (const float*)d_in[2];
    const float* W2 = (const float*)d_in[3];
    const float* b2 = (const float*)d_in[4];
    float* out = (float*)d_out;

    prep_kernel<<<dim3(32, 4), 256>>>(x, W1, b1);

    cudaLaunchConfig_t cfg = {};
    cfg.gridDim  = dim3(NUNITS);
    cfg.blockDim = dim3(256);
    cfg.dynamicSmemBytes = 0;
    cfg.stream = 0;
    cudaLaunchAttribute attr[1];
    attr[0].id = cudaLaunchAttributeProgrammaticStreamSerialization;
    attr[0].val.programmaticStreamSerializationAllowed = 1;
    cfg.attrs = attr;
    cfg.numAttrs = 1;
    cudaLaunchKernelEx(&cfg, pair_kernel, W2, b2, (float*)out);
}